// round 1
// baseline (speedup 1.0000x reference)
#include <cuda_runtime.h>
#include <math.h>

#define NN 50000
#define EE 600000
#define DD 128
#define CC 8
#define SCALEF 0.08838834764831845f   // 128^-0.5

// ---------------- static device scratch (no allocations allowed) ----------------
__device__ __align__(16) int   g_deg[NN];
__device__ __align__(16) int   g_rowptr[NN + 1];
__device__ __align__(16) int   g_cursor[NN];
__device__ __align__(16) int   g_eids[EE];
__device__ __align__(16) float g_WkT[DD * DD];
__device__ __align__(16) float g_Wqk[DD * DD];
__device__ __align__(16) float g_Wvo[DD * DD];
__device__ __align__(16) float g_bqk[DD];
__device__ __align__(16) float g_bvo[DD];
__device__ __align__(16) float g_wqbk[DD];
__device__            float g_bqbk;
__device__ __align__(16) float g_qp[(size_t)NN * DD];
__device__ __align__(16) float g_qb[NN];
__device__ __align__(16) float g_attn[EE];
__device__ __align__(16) int   g_assign[EE];
__device__ __align__(16) float g_denom[CC * NN];
__device__ __align__(16) int   g_cnt[CC * NN];
__device__            int   g_mask;
__device__            float g_invnn;
__device__ __align__(16) float g_coeff[EE];
__device__ __align__(16) float g_U[(size_t)NN * DD];
__device__ __align__(16) float g_S[NN];

// ---------------- init: zero per-call accumulators ----------------
__global__ void k_init() {
    int i = blockIdx.x * blockDim.x + threadIdx.x;
    int stride = gridDim.x * blockDim.x;
    for (int t = i; t < CC * NN; t += stride) { g_denom[t] = 0.f; g_cnt[t] = 0; }
    for (int t = i; t < NN; t += stride) g_deg[t] = 0;
    if (i == 0) g_mask = 0;
}

// ---------------- CSR build ----------------
__global__ void k_hist(const int* __restrict__ src) {
    int i = blockIdx.x * blockDim.x + threadIdx.x;
    if (i < EE) atomicAdd(&g_deg[src[i]], 1);
}

__global__ void k_scan() {
    __shared__ int sums[1024];
    int tid = threadIdx.x;
    const int CH = (NN + 1023) / 1024;
    int s0 = tid * CH;
    int s1 = s0 + CH; if (s1 > NN) s1 = NN;
    int s = 0;
    for (int i = s0; i < s1; i++) s += g_deg[i];
    sums[tid] = s;
    __syncthreads();
    for (int off = 1; off < 1024; off <<= 1) {
        int v = (tid >= off) ? sums[tid - off] : 0;
        __syncthreads();
        sums[tid] += v;
        __syncthreads();
    }
    int base = (tid == 0) ? 0 : sums[tid - 1];
    for (int i = s0; i < s1; i++) {
        g_rowptr[i] = base; g_cursor[i] = base;
        base += g_deg[i];
    }
    if (tid == 1023) g_rowptr[NN] = sums[1023];
}

__global__ void k_scatter(const int* __restrict__ src) {
    int i = blockIdx.x * blockDim.x + threadIdx.x;
    if (i < EE) {
        int p = atomicAdd(&g_cursor[src[i]], 1);
        g_eids[p] = i;
    }
}

// ---------------- weight precompute ----------------
__global__ void k_transpose(const float* __restrict__ Wk) {
    int i = blockIdx.x * blockDim.x + threadIdx.x;
    if (i < DD * DD) {
        int r = i / DD, c = i % DD;
        g_WkT[c * DD + r] = Wk[i];
    }
}

__global__ void k_vecprep(const float* __restrict__ Wq, const float* __restrict__ bq,
                          const float* __restrict__ Wk, const float* __restrict__ bk,
                          const float* __restrict__ bv, const float* __restrict__ Wo) {
    int j = threadIdx.x;   // 0..127
    float s1 = 0.f, s2 = 0.f, s3 = 0.f;
    for (int l = 0; l < DD; l++) {
        s1 += bq[l] * Wk[j * DD + l];      // bqk  = bq @ Wk^T
        s2 += bv[l] * Wo[l * DD + j];      // bvo  = bv @ Wo
        s3 += Wq[j * DD + l] * bk[l];      // wqbk = Wq @ bk
    }
    g_bqk[j] = s1; g_bvo[j] = s2; g_wqbk[j] = s3;
    if (j == 0) {
        float t = 0.f;
        for (int l = 0; l < DD; l++) t += bq[l] * bk[l];
        g_bqbk = t;
    }
}

// ---------------- generic [M,128] @ [128,128] FFMA GEMM ----------------
// out[row] = relu?( A[row] @ W + bias + rowscale[row]*vecterm )
// block = 128 threads, M_TILE = 64 rows, thread computes 8 rows x 8 cols.
__global__ void k_gemm128(const float* __restrict__ A, const float* __restrict__ W,
                          const float* __restrict__ bias, const float* __restrict__ rowscale,
                          const float* __restrict__ vecterm, float* __restrict__ out,
                          int M, int doRelu) {
    extern __shared__ float smem[];
    float4* Ws4 = (float4*)smem;                 // 128*128 floats
    float4* As4 = (float4*)(smem + DD * DD);     // 64*128 floats

    for (int i = threadIdx.x; i < DD * DD / 4; i += blockDim.x)
        Ws4[i] = ((const float4*)W)[i];
    __syncthreads();

    int r = threadIdx.x >> 4;    // 0..7 row group
    int jc = threadIdx.x & 15;   // 0..15 col group (8 cols)

    for (int tile = blockIdx.x; tile * 64 < M; tile += gridDim.x) {
        int row0 = tile * 64;
        for (int i = threadIdx.x; i < 64 * 32; i += blockDim.x) {
            int rr = i >> 5, cc = i & 31;
            float4 v = make_float4(0.f, 0.f, 0.f, 0.f);
            if (row0 + rr < M) v = ((const float4*)A)[(size_t)(row0 + rr) * 32 + cc];
            As4[i] = v;
        }
        __syncthreads();

        float acc[8][8];
#pragma unroll
        for (int a = 0; a < 8; a++)
#pragma unroll
            for (int b = 0; b < 8; b++) acc[a][b] = 0.f;

#pragma unroll 4
        for (int k4 = 0; k4 < 32; k4++) {
            float4 a4[8];
#pragma unroll
            for (int rr = 0; rr < 8; rr++) a4[rr] = As4[(r * 8 + rr) * 32 + k4];
#pragma unroll
            for (int kk = 0; kk < 4; kk++) {
                float4 wA = Ws4[(k4 * 4 + kk) * 32 + jc * 2];
                float4 wB = Ws4[(k4 * 4 + kk) * 32 + jc * 2 + 1];
#pragma unroll
                for (int rr = 0; rr < 8; rr++) {
                    float av = (kk == 0) ? a4[rr].x : (kk == 1) ? a4[rr].y
                             : (kk == 2) ? a4[rr].z : a4[rr].w;
                    acc[rr][0] += av * wA.x; acc[rr][1] += av * wA.y;
                    acc[rr][2] += av * wA.z; acc[rr][3] += av * wA.w;
                    acc[rr][4] += av * wB.x; acc[rr][5] += av * wB.y;
                    acc[rr][6] += av * wB.z; acc[rr][7] += av * wB.w;
                }
            }
        }

        float4 b0 = make_float4(0, 0, 0, 0), b1 = make_float4(0, 0, 0, 0);
        float4 v0 = make_float4(0, 0, 0, 0), v1 = make_float4(0, 0, 0, 0);
        if (bias)    { b0 = ((const float4*)bias)[jc * 2];    b1 = ((const float4*)bias)[jc * 2 + 1]; }
        if (vecterm) { v0 = ((const float4*)vecterm)[jc * 2]; v1 = ((const float4*)vecterm)[jc * 2 + 1]; }

#pragma unroll
        for (int rr = 0; rr < 8; rr++) {
            int row = row0 + r * 8 + rr;
            if (row < M) {
                float sc = rowscale ? rowscale[row] : 0.f;
                float o0 = acc[rr][0] + b0.x + sc * v0.x;
                float o1 = acc[rr][1] + b0.y + sc * v0.y;
                float o2 = acc[rr][2] + b0.z + sc * v0.z;
                float o3 = acc[rr][3] + b0.w + sc * v0.w;
                float o4 = acc[rr][4] + b1.x + sc * v1.x;
                float o5 = acc[rr][5] + b1.y + sc * v1.y;
                float o6 = acc[rr][6] + b1.z + sc * v1.z;
                float o7 = acc[rr][7] + b1.w + sc * v1.w;
                if (doRelu) {
                    o0 = fmaxf(o0, 0.f); o1 = fmaxf(o1, 0.f); o2 = fmaxf(o2, 0.f); o3 = fmaxf(o3, 0.f);
                    o4 = fmaxf(o4, 0.f); o5 = fmaxf(o5, 0.f); o6 = fmaxf(o6, 0.f); o7 = fmaxf(o7, 0.f);
                }
                ((float4*)out)[(size_t)row * 32 + jc * 2]     = make_float4(o0, o1, o2, o3);
                ((float4*)out)[(size_t)row * 32 + jc * 2 + 1] = make_float4(o4, o5, o6, o7);
            }
        }
        __syncthreads();
    }
}

// ---------------- per-node scalar qb[n] = node_feat[n] . wqbk + bqbk ----------------
__global__ void k_qb(const float* __restrict__ nf) {
    int w = (blockIdx.x * blockDim.x + threadIdx.x) >> 5;
    int lane = threadIdx.x & 31;
    if (w >= NN) return;
    float4 a = ((const float4*)nf)[(size_t)w * 32 + lane];
    float4 b = ((const float4*)g_wqbk)[lane];
    float p = a.x * b.x + a.y * b.y + a.z * b.z + a.w * b.w;
#pragma unroll
    for (int off = 16; off; off >>= 1) p += __shfl_xor_sync(0xffffffffu, p, off);
    if (lane == 0) g_qb[w] = p + g_bqbk;
}

// ---------------- pass1: warp per edge -> attn, assign, denom, cnt ----------------
__global__ void k_pass1(const float* __restrict__ tf, const int* __restrict__ src,
                        const float* __restrict__ cemb) {
    __shared__ float4 emb_s[CC * 32];
    for (int i = threadIdx.x; i < CC * 32; i += blockDim.x)
        emb_s[i] = ((const float4*)cemb)[i];
    __syncthreads();

    int e = (blockIdx.x * blockDim.x + threadIdx.x) >> 5;
    int lane = threadIdx.x & 31;
    if (e >= EE) return;

    float4 t4 = ((const float4*)tf)[(size_t)e * 32 + lane];
    int s = src[e];
    float4 q4 = ((const float4*)g_qp)[(size_t)s * 32 + lane];

    float p[9];
#pragma unroll
    for (int c = 0; c < CC; c++) {
        float4 e4 = emb_s[c * 32 + lane];
        p[c] = t4.x * e4.x + t4.y * e4.y + t4.z * e4.z + t4.w * e4.w;
    }
    p[8] = t4.x * q4.x + t4.y * q4.y + t4.z * q4.z + t4.w * q4.w;

#pragma unroll
    for (int i = 0; i < 9; i++) {
#pragma unroll
        for (int off = 16; off; off >>= 1)
            p[i] += __shfl_xor_sync(0xffffffffu, p[i], off);
    }

    if (lane == 0) {
        int best = 0; float bvv = p[0];
#pragma unroll
        for (int c = 1; c < CC; c++) if (p[c] > bvv) { bvv = p[c]; best = c; }
        float a = (p[8] + g_qb[s]) * SCALEF;
        g_attn[e] = a;
        g_assign[e] = best;
        int seg = best * NN + s;
        atomicAdd(&g_denom[seg], expf(a));   // softmax without max-sub: identical result
        atomicAdd(&g_cnt[seg], 1);
    }
}

// ---------------- nonempty clusters -> inv num_nonempty ----------------
__global__ void k_nonempty() {
    int i = blockIdx.x * blockDim.x + threadIdx.x;
    int stride = gridDim.x * blockDim.x;
    unsigned f = 0;
    for (int t = i; t < CC * NN; t += stride)
        if (g_cnt[t] != 0) f |= 1u << (t / NN);
#pragma unroll
    for (int off = 16; off; off >>= 1) f |= __shfl_xor_sync(0xffffffffu, f, off);
    if ((threadIdx.x & 31) == 0 && f) atomicOr(&g_mask, (int)f);
}

__global__ void k_invnn() {
    int nn = __popc(g_mask);
    if (nn < 1) nn = 1;
    g_invnn = 1.0f / (float)nn;
}

// ---------------- per-edge coefficient = softmax-weight / count / num_nonempty ----------------
__global__ void k_coeff(const int* __restrict__ src) {
    int e = blockIdx.x * blockDim.x + threadIdx.x;
    if (e < EE) {
        int s = src[e];
        int seg = g_assign[e] * NN + s;
        float w = expf(g_attn[e]) / g_denom[seg];
        g_coeff[e] = w / (float)g_cnt[seg] * g_invnn;
    }
}

// ---------------- pass2: CSR gather, block per node -> U, S (no atomics) ----------------
__global__ void k_pass2(const float* __restrict__ tf) {
    int n = blockIdx.x;
    int j = threadIdx.x;   // 0..127
    int beg = g_rowptr[n], end = g_rowptr[n + 1];
    float acc = 0.f, sc = 0.f;
    for (int k = beg; k < end; k++) {
        int e = g_eids[k];
        float cf = __ldg(&g_coeff[e]);
        acc += cf * __ldg(&tf[(size_t)e * DD + j]);
        sc += cf;
    }
    g_U[(size_t)n * DD + j] = acc;
    if (j == 0) g_S[n] = sc;
}

// ---------------- launch ----------------
extern "C" void kernel_launch(void* const* d_in, const int* in_sizes, int n_in,
                              void* d_out, int out_size) {
    const float* node_feat = (const float*)d_in[0];
    const float* time_feat = (const float*)d_in[1];
    // d_in[2] context_feat: unused by reference
    const int*   edge_index = (const int*)d_in[3];
    const float* Wq = (const float*)d_in[4];
    const float* bq = (const float*)d_in[5];
    const float* Wk = (const float*)d_in[6];
    const float* bk = (const float*)d_in[7];
    const float* Wv = (const float*)d_in[8];
    const float* bv = (const float*)d_in[9];
    const float* cemb = (const float*)d_in[10];
    const float* Wo = (const float*)d_in[11];
    const float* bo = (const float*)d_in[12];
    const int* src = edge_index;           // row 0 of [2,E]
    float* out = (float*)d_out;

    void *pWkT, *pWqk, *pWvo, *pbqk, *pbvo, *pqp, *pU, *pS;
    cudaGetSymbolAddress(&pWkT, g_WkT);
    cudaGetSymbolAddress(&pWqk, g_Wqk);
    cudaGetSymbolAddress(&pWvo, g_Wvo);
    cudaGetSymbolAddress(&pbqk, g_bqk);
    cudaGetSymbolAddress(&pbvo, g_bvo);
    cudaGetSymbolAddress(&pqp,  g_qp);
    cudaGetSymbolAddress(&pU,   g_U);
    cudaGetSymbolAddress(&pS,   g_S);

    const int smemGemm = (DD * DD + 64 * DD) * (int)sizeof(float);   // 96 KB
    cudaFuncSetAttribute(k_gemm128, cudaFuncAttributeMaxDynamicSharedMemorySize, smemGemm);

    k_init<<<1563, 256>>>();
    k_hist<<<(EE + 255) / 256, 256>>>(src);
    k_scan<<<1, 1024>>>();
    k_scatter<<<(EE + 255) / 256, 256>>>(src);

    k_transpose<<<(DD * DD + 255) / 256, 256>>>(Wk);
    k_gemm128<<<2, 128, smemGemm>>>(Wq, (const float*)pWkT, nullptr, nullptr, nullptr,
                                    (float*)pWqk, DD, 0);
    k_gemm128<<<2, 128, smemGemm>>>(Wv, Wo, nullptr, nullptr, nullptr,
                                    (float*)pWvo, DD, 0);
    k_vecprep<<<1, 128>>>(Wq, bq, Wk, bk, bv, Wo);

    k_gemm128<<<(NN + 63) / 64, 128, smemGemm>>>(node_feat, (const float*)pWqk,
                                                 (const float*)pbqk, nullptr, nullptr,
                                                 (float*)pqp, NN, 0);
    k_qb<<<(NN * 32 + 255) / 256, 256>>>(node_feat);

    k_pass1<<<(EE * 32 + 255) / 256, 256>>>(time_feat, src, cemb);
    k_nonempty<<<512, 256>>>();
    k_invnn<<<1, 1>>>();
    k_coeff<<<(EE + 255) / 256, 256>>>(src);
    k_pass2<<<NN, 128>>>(time_feat);

    k_gemm128<<<(NN + 63) / 64, 128, smemGemm>>>((const float*)pU, (const float*)pWvo,
                                                 bo, (const float*)pS, (const float*)pbvo,
                                                 out, NN, 1);
}

// round 2
// speedup vs baseline: 1.1891x; 1.1891x over previous
#include <cuda_runtime.h>
#include <math.h>

#define NN 50000
#define EE 600000
#define DD 128
#define CC 8
#define SCALEF 0.08838834764831845f   // 128^-0.5

// ---------------- static device scratch ----------------
__device__ __align__(16) int   g_deg[NN];
__device__ __align__(16) int   g_rowptr[NN + 1];
__device__ __align__(16) int   g_cursor[NN];
__device__ __align__(16) int   g_eids[EE];
__device__ __align__(16) float g_ccsr[EE];
__device__ __align__(16) float g_WkT[DD * DD];
__device__ __align__(16) float g_Wqk[DD * DD];
__device__ __align__(16) float g_Wvo[DD * DD];
__device__ __align__(16) float g_bqk[DD];
__device__ __align__(16) float g_bvo[DD];
__device__ __align__(16) float g_wqbk[DD];
__device__            float g_bqbk;
__device__ __align__(16) float g_qp[(size_t)NN * DD];
__device__ __align__(16) float g_qb[NN];
__device__ __align__(16) float g_attn[EE];
__device__ __align__(16) int   g_assign[EE];
__device__ __align__(16) float g_denom[CC * NN];
__device__ __align__(16) int   g_cnt[CC * NN];
__device__            int   g_mask;
__device__            float g_invnn;
__device__ __align__(16) float g_U[(size_t)NN * DD];
__device__ __align__(16) float g_S[NN];

// ---------------- packed f32x2 helpers ----------------
__device__ __forceinline__ unsigned long long pack2(float x) {
    unsigned long long r;
    unsigned u = __float_as_uint(x);
    asm("mov.b64 %0, {%1, %1};" : "=l"(r) : "r"(u));
    return r;
}
__device__ __forceinline__ void ffma2(unsigned long long& d, unsigned long long a,
                                      unsigned long long b) {
    asm("fma.rn.f32x2 %0, %1, %2, %0;" : "+l"(d) : "l"(a), "l"(b));
}
__device__ __forceinline__ void unpack2(unsigned long long v, float& lo, float& hi) {
    unsigned a, b;
    asm("mov.b64 {%0, %1}, %2;" : "=r"(a), "=r"(b) : "l"(v));
    lo = __uint_as_float(a); hi = __uint_as_float(b);
}

// ---------------- init ----------------
__global__ void k_init() {
    int i = blockIdx.x * blockDim.x + threadIdx.x;
    int stride = gridDim.x * blockDim.x;
    for (int t = i; t < CC * NN; t += stride) { g_denom[t] = 0.f; g_cnt[t] = 0; }
    for (int t = i; t < NN; t += stride) g_deg[t] = 0;
    if (i == 0) g_mask = 0;
}

// ---------------- CSR build ----------------
__global__ void k_hist(const int* __restrict__ src) {
    int i = blockIdx.x * blockDim.x + threadIdx.x;
    if (i < EE) atomicAdd(&g_deg[src[i]], 1);
}

__global__ void k_scan() {
    __shared__ int sums[1024];
    int tid = threadIdx.x;
    const int CH = (NN + 1023) / 1024;
    int s0 = tid * CH;
    int s1 = s0 + CH; if (s1 > NN) s1 = NN;
    int s = 0;
    for (int i = s0; i < s1; i++) s += g_deg[i];
    sums[tid] = s;
    __syncthreads();
    for (int off = 1; off < 1024; off <<= 1) {
        int v = (tid >= off) ? sums[tid - off] : 0;
        __syncthreads();
        sums[tid] += v;
        __syncthreads();
    }
    int base = (tid == 0) ? 0 : sums[tid - 1];
    for (int i = s0; i < s1; i++) {
        g_rowptr[i] = base; g_cursor[i] = base;
        base += g_deg[i];
    }
    if (tid == 1023) g_rowptr[NN] = sums[1023];
}

__global__ void k_scatter(const int* __restrict__ src) {
    int i = blockIdx.x * blockDim.x + threadIdx.x;
    if (i < EE) {
        int p = atomicAdd(&g_cursor[src[i]], 1);
        g_eids[p] = i;
    }
}

// ---------------- weight precompute: transpose Wk + bias vectors ----------------
__global__ void k_prep(const float* __restrict__ Wq, const float* __restrict__ bq,
                       const float* __restrict__ Wk, const float* __restrict__ bk,
                       const float* __restrict__ bv, const float* __restrict__ Wo) {
    if (blockIdx.x < DD) {
        int r = blockIdx.x, c = threadIdx.x;
        g_WkT[c * DD + r] = Wk[r * DD + c];
    } else {
        int j = threadIdx.x;
        float s1 = 0.f, s2 = 0.f, s3 = 0.f;
        for (int l = 0; l < DD; l++) {
            s1 += bq[l] * Wk[j * DD + l];      // bqk  = bq @ Wk^T
            s2 += bv[l] * Wo[l * DD + j];      // bvo  = bv @ Wo
            s3 += Wq[j * DD + l] * bk[l];      // wqbk = Wq @ bk
        }
        g_bqk[j] = s1; g_bvo[j] = s2; g_wqbk[j] = s3;
        if (j == 0) {
            float t = 0.f;
            for (int l = 0; l < DD; l++) t += bq[l] * bk[l];
            g_bqbk = t;
        }
    }
}

// ---------------- [M,128] @ [128,128] GEMM with packed f32x2 FMA ----------------
// out[row] = relu?( A[row] @ W + bias + rowscale[row]*vecterm )
__global__ void __launch_bounds__(128, 2)
k_gemm128(const float* __restrict__ A, const float* __restrict__ W,
          const float* __restrict__ bias, const float* __restrict__ rowscale,
          const float* __restrict__ vecterm, float* __restrict__ out,
          int M, int doRelu) {
    extern __shared__ float smem[];
    float4* Ws4 = (float4*)smem;                 // 128*128 floats
    float4* As4 = (float4*)(smem + DD * DD);     // 64*128 floats
    const ulonglong2* WsU = (const ulonglong2*)smem;

    for (int i = threadIdx.x; i < DD * DD / 4; i += blockDim.x)
        Ws4[i] = ((const float4*)W)[i];
    __syncthreads();

    int r = threadIdx.x >> 4;    // 0..7 row group
    int jc = threadIdx.x & 15;   // 0..15 col group (8 cols)

    for (int tile = blockIdx.x; tile * 64 < M; tile += gridDim.x) {
        int row0 = tile * 64;
        for (int i = threadIdx.x; i < 64 * 32; i += blockDim.x) {
            int rr = i >> 5, cc = i & 31;
            float4 v = make_float4(0.f, 0.f, 0.f, 0.f);
            if (row0 + rr < M) v = ((const float4*)A)[(size_t)(row0 + rr) * 32 + cc];
            As4[i] = v;
        }
        __syncthreads();

        unsigned long long acc2[8][4];
#pragma unroll
        for (int a = 0; a < 8; a++)
#pragma unroll
            for (int b = 0; b < 4; b++) acc2[a][b] = 0ull;

#pragma unroll 1
        for (int k4 = 0; k4 < 32; k4++) {
            float4 a4[8];
#pragma unroll
            for (int rr = 0; rr < 8; rr++) a4[rr] = As4[(r * 8 + rr) * 32 + k4];
#pragma unroll
            for (int kk = 0; kk < 4; kk++) {
                int k = k4 * 4 + kk;
                ulonglong2 w01 = WsU[k * 32 + jc * 2];
                ulonglong2 w23 = WsU[k * 32 + jc * 2 + 1];
#pragma unroll
                for (int rr = 0; rr < 8; rr++) {
                    float av = (kk == 0) ? a4[rr].x : (kk == 1) ? a4[rr].y
                             : (kk == 2) ? a4[rr].z : a4[rr].w;
                    unsigned long long av2 = pack2(av);
                    ffma2(acc2[rr][0], av2, w01.x);
                    ffma2(acc2[rr][1], av2, w01.y);
                    ffma2(acc2[rr][2], av2, w23.x);
                    ffma2(acc2[rr][3], av2, w23.y);
                }
            }
        }

        float bv8[8] = {0,0,0,0,0,0,0,0}, vv8[8] = {0,0,0,0,0,0,0,0};
        if (bias) {
            float4 b0 = ((const float4*)bias)[jc * 2], b1 = ((const float4*)bias)[jc * 2 + 1];
            bv8[0]=b0.x; bv8[1]=b0.y; bv8[2]=b0.z; bv8[3]=b0.w;
            bv8[4]=b1.x; bv8[5]=b1.y; bv8[6]=b1.z; bv8[7]=b1.w;
        }
        if (vecterm) {
            float4 v0 = ((const float4*)vecterm)[jc * 2], v1 = ((const float4*)vecterm)[jc * 2 + 1];
            vv8[0]=v0.x; vv8[1]=v0.y; vv8[2]=v0.z; vv8[3]=v0.w;
            vv8[4]=v1.x; vv8[5]=v1.y; vv8[6]=v1.z; vv8[7]=v1.w;
        }

#pragma unroll
        for (int rr = 0; rr < 8; rr++) {
            int row = row0 + r * 8 + rr;
            if (row < M) {
                float sc = rowscale ? rowscale[row] : 0.f;
                float o[8];
#pragma unroll
                for (int c2 = 0; c2 < 4; c2++)
                    unpack2(acc2[rr][c2], o[2 * c2], o[2 * c2 + 1]);
#pragma unroll
                for (int c = 0; c < 8; c++) {
                    o[c] += bv8[c] + sc * vv8[c];
                    if (doRelu) o[c] = fmaxf(o[c], 0.f);
                }
                ((float4*)out)[(size_t)row * 32 + jc * 2]     = make_float4(o[0], o[1], o[2], o[3]);
                ((float4*)out)[(size_t)row * 32 + jc * 2 + 1] = make_float4(o[4], o[5], o[6], o[7]);
            }
        }
        __syncthreads();
    }
}

// ---------------- per-node scalar qb[n] = node_feat[n] . wqbk + bqbk ----------------
__global__ void k_qb(const float* __restrict__ nf) {
    int w = (blockIdx.x * blockDim.x + threadIdx.x) >> 5;
    int lane = threadIdx.x & 31;
    if (w >= NN) return;
    float4 a = ((const float4*)nf)[(size_t)w * 32 + lane];
    float4 b = ((const float4*)g_wqbk)[lane];
    float p = a.x * b.x + a.y * b.y + a.z * b.z + a.w * b.w;
#pragma unroll
    for (int off = 16; off; off >>= 1) p += __shfl_xor_sync(0xffffffffu, p, off);
    if (lane == 0) g_qb[w] = p + g_bqbk;
}

// ---------------- pass1: 8 lanes per edge, 4 edges per warp ----------------
__global__ void k_pass1(const float* __restrict__ tf, const int* __restrict__ src,
                        const float* __restrict__ cemb) {
    __shared__ float4 emb_s[CC * 32];
    for (int i = threadIdx.x; i < CC * 32; i += blockDim.x)
        emb_s[i] = ((const float4*)cemb)[i];
    __syncthreads();

    int gw = (blockIdx.x * blockDim.x + threadIdx.x) >> 5;   // global warp id
    int lane = threadIdx.x & 31;
    int sub = lane >> 3;       // 0..3  edge-within-warp
    int l = lane & 7;          // 0..7  lane-within-edge
    int e = gw * 4 + sub;      // EE divisible by 4; grid sized exactly
    int s = src[e];

    float4 t4[4], q4[4];
#pragma unroll
    for (int u = 0; u < 4; u++) {
        t4[u] = ((const float4*)tf)[(size_t)e * 32 + u * 8 + l];
        q4[u] = ((const float4*)g_qp)[(size_t)s * 32 + u * 8 + l];
    }

    float p[9];
#pragma unroll
    for (int c = 0; c < CC; c++) {
        float acc = 0.f;
#pragma unroll
        for (int u = 0; u < 4; u++) {
            float4 ev = emb_s[c * 32 + u * 8 + l];
            acc += t4[u].x * ev.x + t4[u].y * ev.y + t4[u].z * ev.z + t4[u].w * ev.w;
        }
        p[c] = acc;
    }
    {
        float acc = 0.f;
#pragma unroll
        for (int u = 0; u < 4; u++)
            acc += t4[u].x * q4[u].x + t4[u].y * q4[u].y + t4[u].z * q4[u].z + t4[u].w * q4[u].w;
        p[8] = acc;
    }

#pragma unroll
    for (int i = 0; i < 9; i++) {
#pragma unroll
        for (int off = 4; off; off >>= 1)
            p[i] += __shfl_xor_sync(0xffffffffu, p[i], off);
    }

    if (l == 0) {
        int best = 0; float bvv = p[0];
#pragma unroll
        for (int c = 1; c < CC; c++) if (p[c] > bvv) { bvv = p[c]; best = c; }
        float a = (p[8] + g_qb[s]) * SCALEF;
        g_attn[e] = a;
        g_assign[e] = best;
        int seg = best * NN + s;
        atomicAdd(&g_denom[seg], __expf(a));
        atomicAdd(&g_cnt[seg], 1);
    }
}

// ---------------- nonempty clusters ----------------
__global__ void k_nonempty() {
    int i = blockIdx.x * blockDim.x + threadIdx.x;
    int stride = gridDim.x * blockDim.x;
    unsigned f = 0;
    for (int t = i; t < CC * NN; t += stride)
        if (g_cnt[t] != 0) f |= 1u << (t / NN);
#pragma unroll
    for (int off = 16; off; off >>= 1) f |= __shfl_xor_sync(0xffffffffu, f, off);
    if ((threadIdx.x & 31) == 0 && f) atomicOr(&g_mask, (int)f);
}

__global__ void k_invnn() {
    int nn = __popc(g_mask);
    if (nn < 1) nn = 1;
    g_invnn = 1.0f / (float)nn;
}

// ---------------- coefficients in CSR order ----------------
__global__ void k_coeff_csr(const int* __restrict__ src) {
    int i = blockIdx.x * blockDim.x + threadIdx.x;
    if (i < EE) {
        int e = g_eids[i];
        int s = src[e];
        int seg = g_assign[e] * NN + s;
        float w = __expf(g_attn[e]) / g_denom[seg];
        g_ccsr[i] = w / (float)g_cnt[seg] * g_invnn;
    }
}

// ---------------- pass2: CSR gather, block per node, MLP-8 unrolled ----------------
__global__ void k_pass2(const float* __restrict__ tf) {
    int n = blockIdx.x;
    int j = threadIdx.x;   // 0..127
    int beg = g_rowptr[n], end = g_rowptr[n + 1];
    float acc = 0.f, sc = 0.f;
    int k = beg;
    for (; k + 8 <= end; k += 8) {
        int e[8]; float c[8], v[8];
#pragma unroll
        for (int u = 0; u < 8; u++) {
            e[u] = __ldg(&g_eids[k + u]);
            c[u] = __ldg(&g_ccsr[k + u]);
        }
#pragma unroll
        for (int u = 0; u < 8; u++) v[u] = __ldg(&tf[(size_t)e[u] * DD + j]);
#pragma unroll
        for (int u = 0; u < 8; u++) { acc += c[u] * v[u]; sc += c[u]; }
    }
    for (; k + 4 <= end; k += 4) {
        int e[4]; float c[4], v[4];
#pragma unroll
        for (int u = 0; u < 4; u++) {
            e[u] = __ldg(&g_eids[k + u]);
            c[u] = __ldg(&g_ccsr[k + u]);
        }
#pragma unroll
        for (int u = 0; u < 4; u++) v[u] = __ldg(&tf[(size_t)e[u] * DD + j]);
#pragma unroll
        for (int u = 0; u < 4; u++) { acc += c[u] * v[u]; sc += c[u]; }
    }
    for (; k < end; k++) {
        int e = __ldg(&g_eids[k]);
        float c = __ldg(&g_ccsr[k]);
        acc += c * __ldg(&tf[(size_t)e * DD + j]);
        sc += c;
    }
    g_U[(size_t)n * DD + j] = acc;
    if (j == 0) g_S[n] = sc;
}

// ---------------- launch ----------------
extern "C" void kernel_launch(void* const* d_in, const int* in_sizes, int n_in,
                              void* d_out, int out_size) {
    const float* node_feat = (const float*)d_in[0];
    const float* time_feat = (const float*)d_in[1];
    const int*   edge_index = (const int*)d_in[3];
    const float* Wq = (const float*)d_in[4];
    const float* bq = (const float*)d_in[5];
    const float* Wk = (const float*)d_in[6];
    const float* bk = (const float*)d_in[7];
    const float* Wv = (const float*)d_in[8];
    const float* bv = (const float*)d_in[9];
    const float* cemb = (const float*)d_in[10];
    const float* Wo = (const float*)d_in[11];
    const float* bo = (const float*)d_in[12];
    const int* src = edge_index;           // row 0 of [2,E]
    float* out = (float*)d_out;

    void *pWkT, *pWqk, *pWvo, *pbqk, *pbvo, *pqp, *pU, *pS;
    cudaGetSymbolAddress(&pWkT, g_WkT);
    cudaGetSymbolAddress(&pWqk, g_Wqk);
    cudaGetSymbolAddress(&pWvo, g_Wvo);
    cudaGetSymbolAddress(&pbqk, g_bqk);
    cudaGetSymbolAddress(&pbvo, g_bvo);
    cudaGetSymbolAddress(&pqp,  g_qp);
    cudaGetSymbolAddress(&pU,   g_U);
    cudaGetSymbolAddress(&pS,   g_S);

    const int smemGemm = (DD * DD + 64 * DD) * (int)sizeof(float);   // 96 KB
    cudaFuncSetAttribute(k_gemm128, cudaFuncAttributeMaxDynamicSharedMemorySize, smemGemm);

    k_init<<<1563, 256>>>();
    k_hist<<<(EE + 255) / 256, 256>>>(src);
    k_scan<<<1, 1024>>>();
    k_scatter<<<(EE + 255) / 256, 256>>>(src);

    k_prep<<<DD + 1, 128>>>(Wq, bq, Wk, bk, bv, Wo);
    k_gemm128<<<2, 128, smemGemm>>>(Wq, (const float*)pWkT, nullptr, nullptr, nullptr,
                                    (float*)pWqk, DD, 0);
    k_gemm128<<<2, 128, smemGemm>>>(Wv, Wo, nullptr, nullptr, nullptr,
                                    (float*)pWvo, DD, 0);

    k_gemm128<<<(NN + 63) / 64, 128, smemGemm>>>(node_feat, (const float*)pWqk,
                                                 (const float*)pbqk, nullptr, nullptr,
                                                 (float*)pqp, NN, 0);
    k_qb<<<(NN * 32 + 255) / 256, 256>>>(node_feat);

    k_pass1<<<EE / 32, 256>>>(time_feat, src, cemb);   // 4 edges/warp, 8 warps/block
    k_nonempty<<<512, 256>>>();
    k_invnn<<<1, 1>>>();
    k_coeff_csr<<<(EE + 255) / 256, 256>>>(src);
    k_pass2<<<NN, 128>>>(time_feat);

    k_gemm128<<<(NN + 63) / 64, 128, smemGemm>>>((const float*)pU, (const float*)pWvo,
                                                 bo, (const float*)pS, (const float*)pbvo,
                                                 out, NN, 1);
}